// round 7
// baseline (speedup 1.0000x reference)
#include <cuda_runtime.h>
#include <cuda_bf16.h>

#define N_NODES 100000
#define N_EDGES 1600000
#define D_IN    128
#define D_HID   64
#define NB      ((N_NODES + 255) / 256)   // 391 scan blocks

// Scratch (allocation-free rule: __device__ globals)
__device__ int   g_stride;                        // 1 = edge_index int32, 2 = int64
__device__ int   g_cnt [N_NODES];                 // incoming-edge count (no self-loop)
__device__ int   g_off [N_NODES];                 // CSR exclusive offsets
__device__ int   g_cur [N_NODES];                 // fill cursors
__device__ int   g_bsum[512];
__device__ int   g_boff[512];
__device__ int   g_csr [N_EDGES];                 // src ids bucketed by dst
__device__ float g_dis [N_NODES];                 // deg^{-1/2}
__device__ float g_h   [(size_t)N_NODES * D_HID]; // h' = (x@W1)*dis[row]
__device__ float g_t   [N_NODES];                 // t' = (relu(out1)@W2)*dis

__device__ __forceinline__ int clampN(int v) {
    v = v < 0 ? 0 : v;
    return v >= N_NODES ? N_NODES - 1 : v;
}

// ---------------------------------------------------------------- dtype detect
// If edge_index is int64, every odd 32-bit word in the first half is a hi-word
// of an id < 100000 -> 0. If int32, odd words are random node ids.
__global__ void k_detect(const int* __restrict__ ei) {
    __shared__ int nz;
    if (threadIdx.x == 0) nz = 0;
    __syncthreads();
    // sample 2048 odd words spread over the first 3.2M ints (safe for both dtypes)
    for (int i = threadIdx.x; i < 2048; i += 256) {
        size_t e = (size_t)i * (N_EDGES / 2048);      // e in [0, 1.6M)
        if (ei[2 * e + 1] != 0) atomicAdd(&nz, 1);
    }
    __syncthreads();
    if (threadIdx.x == 0) g_stride = (nz == 0) ? 2 : 1;
}

// edge accessors (lo word is the value in both layouts, little-endian)
__device__ __forceinline__ int edge_src(const int* ei, int e, int s) {
    return clampN(ei[(size_t)e * s]);
}
__device__ __forceinline__ int edge_dst(const int* ei, int e, int s) {
    return clampN(ei[(size_t)(N_EDGES + e) * s]);
}

// ---------------------------------------------------------------- degree / counts
__global__ void k_cnt_init() {
    int i = blockIdx.x * 256 + threadIdx.x;
    if (i < N_NODES) g_cnt[i] = 0;
}

__global__ void k_deg(const int* __restrict__ ei) {
    int e = blockIdx.x * 256 + threadIdx.x;
    if (e < N_EDGES) atomicAdd(&g_cnt[edge_dst(ei, e, g_stride)], 1);
}

__global__ void k_dis() {
    int i = blockIdx.x * 256 + threadIdx.x;
    if (i < N_NODES) g_dis[i] = rsqrtf((float)g_cnt[i] + 1.0f);  // +1 self-loop
}

// ---------------------------------------------------------------- 3-phase exclusive scan of g_cnt
__global__ void k_scan1() {
    __shared__ int s[256];
    int t = threadIdx.x, i = blockIdx.x * 256 + t;
    int c = (i < N_NODES) ? g_cnt[i] : 0;
    s[t] = c; __syncthreads();
#pragma unroll
    for (int d = 1; d < 256; d <<= 1) {
        int v = (t >= d) ? s[t - d] : 0;
        __syncthreads();
        s[t] += v;
        __syncthreads();
    }
    if (i < N_NODES) g_off[i] = s[t] - c;       // exclusive within block
    if (t == 255) g_bsum[blockIdx.x] = s[255];  // block total
}

__global__ void k_scan2() {
    __shared__ int s[512];
    int t = threadIdx.x;
    int c = (t < NB) ? g_bsum[t] : 0;
    s[t] = c; __syncthreads();
#pragma unroll
    for (int d = 1; d < 512; d <<= 1) {
        int v = (t >= d) ? s[t - d] : 0;
        __syncthreads();
        s[t] += v;
        __syncthreads();
    }
    if (t < NB) g_boff[t] = s[t] - c;           // exclusive block offsets
}

__global__ void k_scan3() {
    int i = blockIdx.x * 256 + threadIdx.x;
    if (i < N_NODES) {
        int o = g_off[i] + g_boff[blockIdx.x];
        g_off[i] = o;
        g_cur[i] = o;
    }
}

// ---------------------------------------------------------------- CSR fill (int atomics only)
__global__ void k_fill(const int* __restrict__ ei) {
    int e = blockIdx.x * 256 + threadIdx.x;
    if (e < N_EDGES) {
        int s = g_stride;
        int d = edge_dst(ei, e, s);
        int pos = atomicAdd(&g_cur[d], 1);
        g_csr[pos] = edge_src(ei, e, s);
    }
}

// ---------------------------------------------------------------- h' = (x@W1)*dis
// 256 threads = 8 warps, 4 rows/warp -> 32 rows/block. W1 + x staged in smem (48KB).
__global__ void k_gemm(const float* __restrict__ x, const float* __restrict__ W1) {
    __shared__ float sW[D_IN * D_HID];
    __shared__ float sx[32 * D_IN];
    int tid = threadIdx.x;
    for (int idx = tid; idx < D_IN * D_HID; idx += 256) sW[idx] = W1[idx];
    int base = blockIdx.x * 32;
    for (int idx = tid; idx < 32 * D_IN; idx += 256) {
        int r = base + (idx >> 7);
        sx[idx] = (r < N_NODES) ? x[(size_t)r * D_IN + (idx & 127)] : 0.f;
    }
    __syncthreads();

    int warp = tid >> 5, lane = tid & 31;
    const float* xs = &sx[warp * 4 * D_IN];
    float a00 = 0.f, a01 = 0.f, a10 = 0.f, a11 = 0.f;
    float a20 = 0.f, a21 = 0.f, a30 = 0.f, a31 = 0.f;

#pragma unroll 8
    for (int k = 0; k < D_IN; k++) {
        float w0 = sW[k * D_HID + lane];
        float w1 = sW[k * D_HID + lane + 32];
        float v0 = xs[k];
        float v1 = xs[D_IN + k];
        float v2 = xs[2 * D_IN + k];
        float v3 = xs[3 * D_IN + k];
        a00 += v0 * w0; a01 += v0 * w1;
        a10 += v1 * w0; a11 += v1 * w1;
        a20 += v2 * w0; a21 += v2 * w1;
        a30 += v3 * w0; a31 += v3 * w1;
    }

    int row = base + warp * 4;
#define GNN_EPI(R, A0, A1)                               \
    {                                                    \
        int rr = row + (R);                              \
        if (rr < N_NODES) {                              \
            float dd = g_dis[rr];                        \
            size_t o = (size_t)rr * D_HID + lane;        \
            g_h[o]      = (A0) * dd;                     \
            g_h[o + 32] = (A1) * dd;                     \
        }                                                \
    }
    GNN_EPI(0, a00, a01)
    GNN_EPI(1, a10, a11)
    GNN_EPI(2, a20, a21)
    GNN_EPI(3, a30, a31)
#undef GNN_EPI
}

// ---------------------------------------------------------------- layer-1 gather + node op (fused)
// One warp per dst node. acc init = h'[n] (self-loop); gather h'[src] over CSR range.
// Epilogue: relu(dis*acc + b1), dot W2, warp-reduce, t' = dot * dis.
__global__ void k_gather1(const float* __restrict__ b1, const float* __restrict__ W2) {
    int n = (blockIdx.x * 256 + threadIdx.x) >> 5;
    int lane = threadIdx.x & 31;
    if (n >= N_NODES) return;

    size_t o = (size_t)n * D_HID + lane;
    float a0 = g_h[o];
    float a1 = g_h[o + 32];

    int beg = g_off[n];
    int end = beg + g_cnt[n];
    int j = beg;
    for (; j + 3 < end; j += 4) {                       // MLP: 8 independent gathers
        int s0 = g_csr[j], s1 = g_csr[j + 1], s2 = g_csr[j + 2], s3 = g_csr[j + 3];
        float p0 = g_h[(size_t)s0 * D_HID + lane], q0 = g_h[(size_t)s0 * D_HID + 32 + lane];
        float p1 = g_h[(size_t)s1 * D_HID + lane], q1 = g_h[(size_t)s1 * D_HID + 32 + lane];
        float p2 = g_h[(size_t)s2 * D_HID + lane], q2 = g_h[(size_t)s2 * D_HID + 32 + lane];
        float p3 = g_h[(size_t)s3 * D_HID + lane], q3 = g_h[(size_t)s3 * D_HID + 32 + lane];
        a0 += (p0 + p1) + (p2 + p3);
        a1 += (q0 + q1) + (q2 + q3);
    }
    for (; j < end; j++) {
        int s = g_csr[j];
        a0 += g_h[(size_t)s * D_HID + lane];
        a1 += g_h[(size_t)s * D_HID + 32 + lane];
    }

    float d = g_dis[n];
    float z0 = fmaxf(fmaf(d, a0, b1[lane]),      0.f);
    float z1 = fmaxf(fmaf(d, a1, b1[lane + 32]), 0.f);
    float t = z0 * W2[lane] + z1 * W2[lane + 32];
#pragma unroll
    for (int off = 16; off; off >>= 1)
        t += __shfl_xor_sync(0xffffffffu, t, off);
    if (lane == 0) g_t[n] = t * d;
}

// ---------------------------------------------------------------- layer-2 gather + padded output (fused)
// One warp per node: scalar gather of t'[src], warp-reduce, write [128]-wide padded row.
__global__ void k_l2(float* __restrict__ out, const float* __restrict__ b2) {
    int n = (blockIdx.x * 256 + threadIdx.x) >> 5;
    int lane = threadIdx.x & 31;
    if (n >= N_NODES) return;

    int beg = g_off[n];
    int end = beg + g_cnt[n];
    float sum = lane ? 0.f : g_t[n];                    // self-loop on lane 0
    for (int j = beg + lane; j < end; j += 32)
        sum += g_t[g_csr[j]];
#pragma unroll
    for (int off = 16; off; off >>= 1)
        sum += __shfl_xor_sync(0xffffffffu, sum, off);

    float y = g_dis[n] * sum + b2[0];
    float4 v = make_float4(0.f, 0.f, 0.f, 0.f);
    if (lane == 0) v.x = y;
    reinterpret_cast<float4*>(out)[(size_t)n * 32 + lane] = v;   // 128 floats/row
}

// ----------------------------------------------------------------
extern "C" void kernel_launch(void* const* d_in, const int* in_sizes, int n_in,
                              void* d_out, int out_size) {
    const float* x   = (const float*)d_in[0];
    const int*   ei  = (const int*)d_in[1];    // int32 OR int64 (detected on device)
    const float* W1  = (const float*)d_in[2];
    const float* b1  = (const float*)d_in[3];
    const float* W2  = (const float*)d_in[4];
    const float* b2  = (const float*)d_in[5];
    float*       out = (float*)d_out;

    k_detect  <<<1, 256>>>(ei);
    k_cnt_init<<<NB, 256>>>();
    k_deg     <<<(N_EDGES + 255) / 256, 256>>>(ei);
    k_dis     <<<NB, 256>>>();
    k_scan1   <<<NB, 256>>>();
    k_scan2   <<<1, 512>>>();
    k_scan3   <<<NB, 256>>>();
    k_fill    <<<(N_EDGES + 255) / 256, 256>>>(ei);
    k_gemm    <<<(N_NODES + 31) / 32, 256>>>(x, W1);
    k_gather1 <<<(N_NODES * 32 + 255) / 256, 256>>>(b1, W2);
    k_l2      <<<(N_NODES * 32 + 255) / 256, 256>>>(out, b2);
}